// round 13
// baseline (speedup 1.0000x reference)
#include <cuda_runtime.h>
#include <cuda_fp16.h>

// Problem constants (fixed shapes from reference)
#define B_   2
#define T_   32
#define C_   128
#define G_   4
#define CPG  32      // channels per head-group = C/G
#define H_   64
#define W_   64
#define HC_  16      // coarse h
#define WC_  16      // coarse w
#define TQ   8       // q-chunk per block
#define HW_  (H_*W_)     // 4096
#define CHW_ (C_*HW_)    // 524288
#define KC   8       // k per staged chunk
#define NCH  (T_/KC) // 4 chunks

typedef unsigned long long u64t;

// out[b,q,g*CPG+c,h,w] = sum_k A_fine[g,b,q,k,h,w] * x[b,k,g*CPG+c,h,w]
// A_fine = bilinear upsample (x4, half-pixel centers, edge clamp) of attn.
// Champion mainloop (R9): q8c4, A as half2 q-pairs, fp32 FFMA2 accumulation.
// This round: x staged GMEM->smem as fp16, double-buffered k8 chunks, so the
// mainloop has NO LDG on its critical path (LDS-only operands).

__device__ __forceinline__ void ffma2(u64t& d, u64t a, u64t b) {
    asm("fma.rn.f32x2 %0, %1, %2, %0;" : "+l"(d) : "l"(a), "l"(b));
}
__device__ __forceinline__ u64t bcast2(float x) {
    u64t d;
    asm("mov.b64 %0, {%1, %1};" : "=l"(d) : "f"(x));
    return d;
}
__device__ __forceinline__ u64t pack2(float lo, float hi) {
    u64t d;
    asm("mov.b64 %0, {%1, %2};" : "=l"(d) : "f"(lo), "f"(hi));
    return d;
}
__device__ __forceinline__ void unpack2(float& lo, float& hi, u64t v) {
    asm("mov.b64 {%0, %1}, %2;" : "=f"(lo), "=f"(hi) : "l"(v));
}

__global__ __launch_bounds__(256, 4) void temporal_agg_kernel(
    const float* __restrict__ x,
    const float* __restrict__ attn,
    float* __restrict__ out)
{
    // xs: 2 buffers x (KC k x 32 c x 32 w) halves = 32 KB. Cy overlays buf0
    // (4096 floats = 16 KB) during phase 1 only.
    __shared__ __align__(16) __half xs[2 * KC * 32 * 32];
    __shared__ __half2 A2h[T_ * 4 * 32];           // [k][qpair][wl]   16 KB
    float* Cy = (float*)xs;                        // [q*32+k][wc], phase-1 only

    const int qc  = blockIdx.x;          // 0..3  (q-chunk)  -- fastest: L2 reuse of x
    const int wch = blockIdx.y;          // 0..1  (w-chunk of 32)
    const int zz  = blockIdx.z;          // (b*G+g)*H + h
    const int h   = zz & (H_ - 1);
    const int bg  = zz >> 6;
    const int g   = bg & (G_ - 1);
    const int b   = bg >> 2;

    const int tid = threadIdx.x;         // 0..255
    const int wl  = tid & 31;

    // ---- y interpolation coefficients for this fine row h ----
    // src_y = (h + 0.5)/4 - 0.5 = h*0.25 - 0.375 ; edge clamp
    float fy  = h * 0.25f - 0.375f;
    float fyf = floorf(fy);
    float wy1 = fy - fyf;
    int   h0  = (int)fyf;
    int   h1  = min(h0 + 1, HC_ - 1);
    h0 = max(h0, 0);

    // ---- phase 1a: Cy[q*32+k][wc] = lerp_y(coarse) ----
    const float* cb = attn + ((((size_t)g * B_ + b) * T_ + (size_t)qc * TQ) * T_) * (HC_ * WC_);
    #pragma unroll
    for (int i = 0; i < (TQ * T_ * WC_) / 256; ++i) {    // 16 iters
        int idx = i * 256 + tid;
        int wc  = idx & (WC_ - 1);
        int qk  = idx >> 4;               // q*32 + k
        const float* p = cb + qk * (HC_ * WC_) + wc;
        float v0 = p[h0 * WC_];
        float v1 = p[h1 * WC_];
        Cy[idx] = fmaf(wy1, v1 - v0, v0);
    }
    __syncthreads();

    // ---- phase 1b: x-lerp + transpose into q-pair half2 A2h[k][qp][wl] ----
    {
        const int wf = wch * 32 + wl;
        float fx  = wf * 0.25f - 0.375f;
        float fxf = floorf(fx);
        float wx1 = fx - fxf;
        int   w0  = (int)fxf;
        int   w1  = min(w0 + 1, WC_ - 1);
        w0 = max(w0, 0);
        const int kb = tid >> 5;                  // 0..7
        #pragma unroll
        for (int i = 0; i < 4; ++i) {
            int k = kb + 8 * i;                   // 0..31
            float a[TQ];
            #pragma unroll
            for (int q = 0; q < TQ; ++q) {
                float v0 = Cy[(q * T_ + k) * WC_ + w0];
                float v1 = Cy[(q * T_ + k) * WC_ + w1];
                a[q] = fmaf(wx1, v1 - v0, v0);
            }
            #pragma unroll
            for (int qp = 0; qp < 4; ++qp)
                A2h[(k * 4 + qp) * 32 + wl] =
                    __floats2half2_rn(a[2 * qp], a[2 * qp + 1]);
        }
    }
    __syncthreads();   // Cy dead after this; xs buffers free

    // ---- x staging setup: thread -> (c = tid>>3, w-quad = tid&7) ----
    const int cw4 = tid & 7;             // 4-float w segment
    const int cc  = tid >> 3;            // 0..31 local channel
    const float* gx0 = x + ((size_t)b * T_ * C_ + g * CPG + cc) * HW_
                         + h * W_ + wch * 32 + cw4 * 4;
    __half* sd0 = xs + cc * 32 + cw4 * 4;   // + buf*8192 + kk*1024

    // prologue: copy chunk 0 -> buf 1 (Cy lives in buf 0 region until now... dead)
    #pragma unroll
    for (int i = 0; i < KC; ++i) {
        float4 v = *(const float4*)(gx0 + (size_t)i * CHW_);
        __half2 p0 = __floats2half2_rn(v.x, v.y);
        __half2 p1 = __floats2half2_rn(v.z, v.w);
        *(uint2*)(sd0 + 8192 + i * 1024) =
            make_uint2(*(unsigned*)&p0, *(unsigned*)&p1);
    }
    __syncthreads();

    // ---- phase 2: double-buffered mainloop, LDS-only operands ----
    const int cg = tid >> 5;                       // 0..7 -> 4 channels each
    const int cbase = g * CPG + cg * 4;
    const int wf = wch * 32 + wl;

    u64t acc[4][4];                                // [qpair][c]
    #pragma unroll
    for (int qp = 0; qp < 4; ++qp)
        #pragma unroll
        for (int c = 0; c < 4; ++c)
            acc[qp][c] = 0ull;

    for (int ch = 0; ch < NCH; ++ch) {             // rolled: small I-footprint
        const int rbuf = (ch & 1) ^ 1;             // 1,0,1,0
        const __half* xb = xs + rbuf * 8192 + cg * 4 * 32 + wl;
        const float* gnext = gx0 + (size_t)(ch + 1) * KC * CHW_;
        __half* snext = sd0 + (rbuf ^ 1) * 8192;
        const bool docopy = (ch < NCH - 1);
        float4 cpv;

        #pragma unroll
        for (int kk = 0; kk < KC; ++kk) {
            if (docopy) {
                if (kk > 0) {
                    __half2 p0 = __floats2half2_rn(cpv.x, cpv.y);
                    __half2 p1 = __floats2half2_rn(cpv.z, cpv.w);
                    *(uint2*)(snext + (kk - 1) * 1024) =
                        make_uint2(*(unsigned*)&p0, *(unsigned*)&p1);
                }
                cpv = *(const float4*)(gnext + (size_t)kk * CHW_);
            }
            const int k = ch * KC + kk;
            u64t xv[4];
            #pragma unroll
            for (int ci = 0; ci < 4; ++ci)
                xv[ci] = bcast2(__half2float(xb[kk * 1024 + ci * 32]));
            u64t av[4];
            #pragma unroll
            for (int qp = 0; qp < 4; ++qp) {
                float2 f = __half22float2(A2h[(k * 4 + qp) * 32 + wl]);
                av[qp] = pack2(f.x, f.y);
            }
            #pragma unroll
            for (int qp = 0; qp < 4; ++qp)
                #pragma unroll
                for (int c = 0; c < 4; ++c)
                    ffma2(acc[qp][c], av[qp], xv[c]);
        }
        if (docopy) {
            __half2 p0 = __floats2half2_rn(cpv.x, cpv.y);
            __half2 p1 = __floats2half2_rn(cpv.z, cpv.w);
            *(uint2*)(snext + (KC - 1) * 1024) =
                make_uint2(*(unsigned*)&p0, *(unsigned*)&p1);
        }
        __syncthreads();
    }

    // ---- store: out[(((b*T+q)*C + c)*H + h)*W + w], q = 2*qp + {0,1} ----
    float* ob = out + (((size_t)b * T_ + (size_t)qc * TQ) * C_ + cbase) * HW_ + h * W_ + wf;
    #pragma unroll
    for (int qp = 0; qp < 4; ++qp) {
        #pragma unroll
        for (int c = 0; c < 4; ++c) {
            float lo, hi;
            unpack2(lo, hi, acc[qp][c]);
            ob[(2 * qp) * CHW_ + c * HW_]     = lo;
            ob[(2 * qp + 1) * CHW_ + c * HW_] = hi;
        }
    }
}

extern "C" void kernel_launch(void* const* d_in, const int* in_sizes, int n_in,
                              void* d_out, int out_size)
{
    const float* x    = (const float*)d_in[0];   // (2,32,128,64,64)
    const float* attn = (const float*)d_in[1];   // (4,2,32,32,16,16)
    float* out        = (float*)d_out;           // (2,32,128,64,64)

    dim3 grid(T_ / TQ /*4 q-chunks*/, W_ / 32 /*2 w-chunks*/, B_ * G_ * H_ /*512*/);
    temporal_agg_kernel<<<grid, 256>>>(x, attn, out);
}

// round 14
// speedup vs baseline: 1.2737x; 1.2737x over previous
#include <cuda_runtime.h>
#include <cuda_fp16.h>

// Problem constants (fixed shapes from reference)
#define B_   2
#define T_   32
#define C_   128
#define G_   4
#define CPG  32      // channels per head-group = C/G
#define H_   64
#define W_   64
#define HC_  16      // coarse h
#define WC_  16      // coarse w
#define TQ   8       // q-chunk per block
#define HW_  (H_*W_)     // 4096
#define CHW_ (C_*HW_)    // 524288

typedef unsigned long long u64t;

// out[b,q,g*CPG+c,h,w] = sum_k A_fine[g,b,q,k,h,w] * x[b,k,g*CPG+c,h,w]
// A_fine = bilinear upsample (x4, half-pixel centers, edge clamp) of attn.
// Champion (R9) mainloop: q8c4 per thread, A as half2 q-pairs (LDS.32, 4B
// lane stride, conflict-free), fp32 FFMA2 accumulation.
// This round: +prefetch.global.L1 of x lines 8 k ahead (streaming prefetch,
// no regs, no deps) to convert mainloop LDG L2-waits into L1 hits.

__device__ __forceinline__ void ffma2(u64t& d, u64t a, u64t b) {
    asm("fma.rn.f32x2 %0, %1, %2, %0;" : "+l"(d) : "l"(a), "l"(b));
}
__device__ __forceinline__ u64t bcast2(float x) {
    u64t d;
    asm("mov.b64 %0, {%1, %1};" : "=l"(d) : "f"(x));
    return d;
}
__device__ __forceinline__ u64t pack2(float lo, float hi) {
    u64t d;
    asm("mov.b64 %0, {%1, %2};" : "=l"(d) : "f"(lo), "f"(hi));
    return d;
}
__device__ __forceinline__ void unpack2(float& lo, float& hi, u64t v) {
    asm("mov.b64 {%0, %1}, %2;" : "=f"(lo), "=f"(hi) : "l"(v));
}
__device__ __forceinline__ void pf_l1(const float* p) {
    asm volatile("prefetch.global.L1 [%0];" :: "l"(p));
}

__global__ __launch_bounds__(256, 4) void temporal_agg_kernel(
    const float* __restrict__ x,
    const float* __restrict__ attn,
    float* __restrict__ out)
{
    __shared__ float   Cy[TQ * T_ * WC_];          // [q*32+k][wc]        16 KB
    __shared__ __half2 A2h[T_ * 4 * 32];           // [k][qpair][wl]      16 KB

    const int qc  = blockIdx.x;          // 0..3  (q-chunk)  -- fastest: L2 reuse of x
    const int wch = blockIdx.y;          // 0..1  (w-chunk of 32)
    const int zz  = blockIdx.z;          // (b*G+g)*H + h
    const int h   = zz & (H_ - 1);
    const int bg  = zz >> 6;
    const int g   = bg & (G_ - 1);
    const int b   = bg >> 2;

    const int tid = threadIdx.x;         // 0..255
    const int wl  = tid & 31;

    // ---- y interpolation coefficients for this fine row h ----
    // src_y = (h + 0.5)/4 - 0.5 = h*0.25 - 0.375 ; edge clamp
    float fy  = h * 0.25f - 0.375f;
    float fyf = floorf(fy);
    float wy1 = fy - fyf;
    int   h0  = (int)fyf;
    int   h1  = min(h0 + 1, HC_ - 1);
    h0 = max(h0, 0);

    // ---- phase 1a: Cy[q*32+k][wc] = lerp_y(coarse) ----
    // coarse attn layout: ((((g*B+b)*T + q)*T + k)*HC + hc)*WC + wc
    const float* cb = attn + ((((size_t)g * B_ + b) * T_ + (size_t)qc * TQ) * T_) * (HC_ * WC_);
    #pragma unroll
    for (int i = 0; i < (TQ * T_ * WC_) / 256; ++i) {    // 16 iters
        int idx = i * 256 + tid;
        int wc  = idx & (WC_ - 1);
        int qk  = idx >> 4;               // q*32 + k
        const float* p = cb + qk * (HC_ * WC_) + wc;
        float v0 = p[h0 * WC_];
        float v1 = p[h1 * WC_];
        Cy[idx] = fmaf(wy1, v1 - v0, v0);
    }
    __syncthreads();

    // ---- phase 1b: x-lerp + transpose into q-pair half2 A2h[k][qp][wl] ----
    {
        const int wf = wch * 32 + wl;
        float fx  = wf * 0.25f - 0.375f;
        float fxf = floorf(fx);
        float wx1 = fx - fxf;
        int   w0  = (int)fxf;
        int   w1  = min(w0 + 1, WC_ - 1);
        w0 = max(w0, 0);
        const int kb = tid >> 5;                  // 0..7
        #pragma unroll
        for (int i = 0; i < 4; ++i) {
            int k = kb + 8 * i;                   // 0..31
            float a[TQ];
            #pragma unroll
            for (int q = 0; q < TQ; ++q) {
                float v0 = Cy[(q * T_ + k) * WC_ + w0];
                float v1 = Cy[(q * T_ + k) * WC_ + w1];
                a[q] = fmaf(wx1, v1 - v0, v0);
            }
            #pragma unroll
            for (int qp = 0; qp < 4; ++qp)
                A2h[(k * 4 + qp) * 32 + wl] =
                    __floats2half2_rn(a[2 * qp], a[2 * qp + 1]);
        }
    }
    __syncthreads();

    // ---- phase 2: per-pixel GEMM slice, f32x2 over q-pairs ----
    // thread: w lane (32), channel group cg (8 warps) -> 4 channels each
    const int cg = tid >> 5;
    const int wf = wch * 32 + wl;
    const int cbase = g * CPG + cg * 4;

    const float* xp = x + ((size_t)b * T_ * C_ + cbase) * HW_ + h * W_ + wf;
    const __half2* ahp = A2h + wl;

    u64t acc[4][4];                     // [qpair][c]
    #pragma unroll
    for (int qp = 0; qp < 4; ++qp)
        #pragma unroll
        for (int c = 0; c < 4; ++c)
            acc[qp][c] = 0ull;

    // warm the prefetch pipeline for k = 0..7
    #pragma unroll
    for (int k = 0; k < 8; ++k)
        pf_l1(xp + k * CHW_);           // first c-line; remaining lines follow in-loop

    #pragma unroll 4
    for (int k = 0; k < T_; ++k) {
        const float* xk = xp + k * CHW_;          // 32-bit offset arithmetic
        // streaming prefetch: 4 c-lines of k+8 (distance ~2 unroll groups)
        if (k < T_ - 8) {
            const float* pf = xk + 8 * CHW_;
            pf_l1(pf);
            pf_l1(pf + HW_);
            pf_l1(pf + 2 * HW_);
            pf_l1(pf + 3 * HW_);
        }
        u64t xv[4];
        #pragma unroll
        for (int c = 0; c < 4; ++c)
            xv[c] = bcast2(xk[c * HW_]);
        u64t av[4];
        #pragma unroll
        for (int qp = 0; qp < 4; ++qp) {
            float2 f = __half22float2(ahp[(k * 4 + qp) * 32]);
            av[qp] = pack2(f.x, f.y);
        }
        #pragma unroll
        for (int qp = 0; qp < 4; ++qp)
            #pragma unroll
            for (int c = 0; c < 4; ++c)
                ffma2(acc[qp][c], av[qp], xv[c]);
    }

    // ---- store: out[(((b*T+q)*C + c)*H + h)*W + w], q = 2*qp + {0,1} ----
    float* ob = out + (((size_t)b * T_ + (size_t)qc * TQ) * C_ + cbase) * HW_ + h * W_ + wf;
    #pragma unroll
    for (int qp = 0; qp < 4; ++qp) {
        #pragma unroll
        for (int c = 0; c < 4; ++c) {
            float lo, hi;
            unpack2(lo, hi, acc[qp][c]);
            ob[(2 * qp) * CHW_ + c * HW_]     = lo;
            ob[(2 * qp + 1) * CHW_ + c * HW_] = hi;
        }
    }
}

extern "C" void kernel_launch(void* const* d_in, const int* in_sizes, int n_in,
                              void* d_out, int out_size)
{
    const float* x    = (const float*)d_in[0];   // (2,32,128,64,64)
    const float* attn = (const float*)d_in[1];   // (4,2,32,32,16,16)
    float* out        = (float*)d_out;           // (2,32,128,64,64)

    dim3 grid(T_ / TQ /*4 q-chunks*/, W_ / 32 /*2 w-chunks*/, B_ * G_ * H_ /*512*/);
    temporal_agg_kernel<<<grid, 256>>>(x, attn, out);
}